// round 16
// baseline (speedup 1.0000x reference)
#include <cuda_runtime.h>
#include <cstdint>

#define B_   2
#define C_   32
#define T_   64
#define HW_  4096
#define N_   512
#define BN_  (B_*N_)         /* 1024 */
#define CH_  16
#define FT_  400
#define L_   (FT_*N_)        /* 204800 */
#define CNT_ (B_*L_)         /* 409600 */
#define OUT_OFF_RESULT ((size_t)B_*CH_*L_)  /* 6,553,600 */

// ---- scratch (device globals) ----
__device__ __align__(16) float g_r[B_*T_*HW_];            // 2 MB
// g_f: quad-plane layout. float4 plane p = t*4 + q, index [p][bn]
__device__ __align__(16) float g_f[(size_t)T_*4*BN_*4];   // 4 MB
__device__ __align__(16) float g_part[32*BN_];            // [col][bn]
__device__ float g_ss[32];                                // sums[16] + sumsqs[16]
__device__ unsigned g_count = 0;
__device__ float g_Weff[C_*CH_];                          // [c][o]
__device__ float g_beff[CH_];
__device__ unsigned g_sorted[BN_];                        // per-b sorted (idx | bn<<16)

// ---- compile-time lerp stat tables (fp32 ops identical to reference) ----
struct LerpTab { float wl[64]; float A[64]; float Bc[64]; float Cc[64]; };
constexpr LerpTab make_tab() {
    LerpTab tb{};
    const float step = (float)(63.0/399.0);
    for (int t = 0; t < FT_; t++) {
        float pos = (float)t * step;
        int i0 = (int)pos;
        int i1 = (i0 + 1 < T_) ? i0 + 1 : T_ - 1;
        float w = pos - (float)i0;
        float w0 = 1.0f - w;
        if (i1 == i0) {
            tb.wl[i0] += (w0 + w);
            tb.A[i0]  += (w0 + w) * (w0 + w);
        } else {
            tb.wl[i0] += w0;  tb.wl[i1] += w;
            tb.A[i0]  += w0 * w0;
            tb.Bc[i0] += 2.0f * w0 * w;
            tb.Cc[i0] += w * w;
        }
    }
    return tb;
}
__constant__ LerpTab c_tab = make_tab();

// ============================================================================
// k_prep (1 block): fold W1@Wf -> g_Weff/g_beff; counting-sort coords by idx
// per batch -> g_sorted (so gather warps read near-contiguous addresses).
// ============================================================================
__global__ void __launch_bounds__(128) k_prep(
    const int* __restrict__ coord,
    const float* __restrict__ W1, const float* __restrict__ Wf,
    const float* __restrict__ b1, const float* __restrict__ bf)
{
    __shared__ unsigned hist[4096];
    __shared__ unsigned tsum[128];
    __shared__ float sW1[CH_*C_], sWf[C_*C_], sbf[C_];
    int tid = threadIdx.x;

    for (int e = tid; e < CH_*C_; e += 128) sW1[e] = W1[e];
    for (int e = tid; e < C_*C_; e += 128) sWf[e] = Wf[e];
    if (tid < 32) sbf[tid] = bf[tid];
    __syncthreads();

    #pragma unroll
    for (int i = 0; i < 4; i++) {
        int e = tid*4 + i;               // 0..511
        int c = e >> 4, o = e & 15;
        float a = 0.f;
        #pragma unroll
        for (int k = 0; k < 32; k++) a += sW1[o*32+k] * sWf[k*32 + c];
        g_Weff[c*CH_+o] = a;
    }
    if (tid < CH_) {
        float bb = b1[tid];
        #pragma unroll
        for (int k = 0; k < 32; k++) bb += sW1[tid*32+k] * sbf[k];
        g_beff[tid] = bb;
    }

    // counting sort per batch
    for (int b = 0; b < B_; b++) {
        __syncthreads();
        for (int i = tid; i < 4096; i += 128) hist[i] = 0;
        __syncthreads();
        for (int e = tid; e < N_; e += 128) {
            int bn = b*N_ + e;
            int idx = coord[bn*2]*64 + coord[bn*2+1];
            atomicAdd(&hist[idx], 1u);
        }
        __syncthreads();
        unsigned local = 0;
        #pragma unroll 8
        for (int i = 0; i < 32; i++) local += hist[tid*32 + i];
        tsum[tid] = local;
        __syncthreads();
        if (tid == 0) {
            unsigned run = 0;
            for (int i = 0; i < 128; i++) { unsigned v = tsum[i]; tsum[i] = run; run += v; }
        }
        __syncthreads();
        {
            unsigned run = tsum[tid];
            #pragma unroll 8
            for (int i = 0; i < 32; i++) {
                unsigned v = hist[tid*32 + i];
                hist[tid*32 + i] = run;
                run += v;
            }
        }
        __syncthreads();
        for (int e = tid; e < N_; e += 128) {
            int bn = b*N_ + e;
            int idx = coord[bn*2]*64 + coord[bn*2+1];
            unsigned pos = atomicAdd(&hist[idx], 1u);
            g_sorted[b*N_ + pos] = (unsigned)idx | ((unsigned)bn << 16);
        }
    }
}

// ============================================================================
// k_main: blocks [0,512) -> transposed gather (warp = 32 sorted samples x 1 t);
//         blocks [512,1536) -> r path (champion code, unchanged).
// ============================================================================
__global__ void __launch_bounds__(128, 8) k_main(
    const float* __restrict__ x,
    const float* __restrict__ Wr, const float* __restrict__ br)
{
    __shared__ float sWe[C_*CH_];    // Weff [c][o]
    __shared__ float sbe[CH_];
    __shared__ float wr[32];

    int bid = blockIdx.x;
    int tid = threadIdx.x;

    if (bid >= 512) {
        // ---- r path: r[b][t][hw] = Wr . x + br (champion, validated) ----
        if (tid < 32) wr[tid] = Wr[tid];
        __syncthreads();
        int gt = (bid - 512)*128 + tid;    // 131072 threads, 4 hw each
        int hw4 = gt & 1023;
        int bt  = gt >> 10;
        int b = bt >> 6, t = bt & 63;
        const float4* xp = (const float4*)(x + (size_t)(b*C_*T_ + t)*HW_) + hw4;
        float brv = br[0];
        float4 acc = make_float4(brv, brv, brv, brv);
        #pragma unroll
        for (int cc = 0; cc < 4; cc++) {
            float4 v[8];
            #pragma unroll
            for (int j = 0; j < 8; j++)
                v[j] = xp[(size_t)(cc*8+j)*T_*(HW_/4)];
            #pragma unroll
            for (int j = 0; j < 8; j++) {
                float wc = wr[cc*8+j];
                acc.x += wc*v[j].x; acc.y += wc*v[j].y;
                acc.z += wc*v[j].z; acc.w += wc*v[j].w;
            }
        }
        ((float4*)g_r)[gt] = acc;
        return;
    }

    // ---- transposed gather: block = (b, group of 32 sorted samples, 4 t) ----
    for (int e = tid; e < C_*CH_; e += 128) sWe[e] = g_Weff[e];
    if (tid < CH_) sbe[tid] = g_beff[tid];
    __syncthreads();

    int b   = bid >> 8;                 // 0..1
    int rem = bid & 255;
    int grp = rem >> 4;                 // 0..15 (sample group)
    int tb  = rem & 15;                 // 0..15 (t block)
    int warp = tid >> 5, lane = tid & 31;
    int t = tb*4 + warp;

    unsigned ent = g_sorted[b*N_ + grp*32 + lane];
    int idx = (int)(ent & 0xffffu);
    int bn  = (int)(ent >> 16);

    const float* xb = x + ((size_t)b*C_*T_ + t)*HW_ + idx;
    float acc[CH_];
    #pragma unroll
    for (int o = 0; o < CH_; o++) acc[o] = sbe[o];

    #pragma unroll
    for (int cc = 0; cc < 4; cc++) {
        float xv[8];
        #pragma unroll
        for (int j = 0; j < 8; j++)
            xv[j] = xb[(size_t)(cc*8+j)*T_*HW_];
        #pragma unroll
        for (int j = 0; j < 8; j++) {
            int c = cc*8 + j;
            #pragma unroll
            for (int o = 0; o < CH_; o++)
                acc[o] += sWe[c*CH_+o] * xv[j];
        }
    }

    float4* gf4 = (float4*)g_f;
    #pragma unroll
    for (int q = 0; q < 4; q++)
        gf4[(size_t)(t*4+q)*BN_ + bn] =
            make_float4(acc[q*4+0], acc[q*4+1], acc[q*4+2], acc[q*4+3]);
}

// ============================================================================
// k_stats: 1024 blocks (one per bn). Load f from g_f (L2-resident), table-based
// lerp stats -> g_part; last block folds -> g_ss. (validated R10 code)
// ============================================================================
__global__ void __launch_bounds__(128, 8) k_stats() {
    __shared__ float sf[T_*CH_];     // [t][o]
    __shared__ float red_s[128];
    __shared__ float red_q[128];
    __shared__ unsigned s_last;

    int bn = blockIdx.x;
    int tid = threadIdx.x;

    #pragma unroll
    for (int i = 0; i < 8; i++) {
        int e = tid + i*128;             // e = t*16 + o
        int t = e >> 4, o = e & 15;
        sf[e] = g_f[((size_t)(t*4 + (o>>2))*BN_ + bn)*4 + (o&3)];
    }
    __syncthreads();

    {
        int o = tid & 15, j = tid >> 4;
        float s_acc = 0.f, q_acc = 0.f;
        #pragma unroll
        for (int k = 0; k < 8; k++) {
            int i  = j + k*8;
            int i1 = (i < 63) ? i + 1 : 63;
            float fi  = sf[i*16 + o];
            float fi1 = sf[i1*16 + o];
            s_acc += c_tab.wl[i] * fi;
            q_acc += c_tab.A[i]*fi*fi + c_tab.Bc[i]*fi*fi1 + c_tab.Cc[i]*fi1*fi1;
        }
        red_s[j*16 + o] = s_acc;
        red_q[j*16 + o] = q_acc;
    }
    __syncthreads();
    if (tid < 32) {
        int c = tid & 15;
        const float* src = (tid < 16) ? red_s : red_q;
        float tot = 0.f;
        #pragma unroll
        for (int jj = 0; jj < 8; jj++) tot += src[jj*16 + c];
        g_part[tid*BN_ + bn] = tot;
    }

    __threadfence();
    if (tid == 0) s_last = (atomicAdd(&g_count, 1u) == 1023u) ? 1u : 0u;
    __syncthreads();
    if (s_last) {
        int c = tid >> 2, qd = tid & 3;
        const float4* p = (const float4*)(g_part + c*BN_) + qd*64;
        float acc = 0.f;
        #pragma unroll 16
        for (int k = 0; k < 64; k++) {
            float4 v4 = p[k];
            acc += (v4.x + v4.y) + (v4.z + v4.w);
        }
        red_s[tid] = acc;
        __syncthreads();
        if (tid < 32) {
            g_ss[tid] = (red_s[tid*4] + red_s[tid*4+1])
                      + (red_s[tid*4+2] + red_s[tid*4+3]);
            if (tid == 0) g_count = 0;   // reset for next graph replay
        }
    }
}

// ============================================================================
// k_fin: blocks [0,1600) -> 2-cell BN+ReLU+W2 epilogue;
//        blocks [1600,4800) -> result lerp. (validated: 16.9 us)
// ============================================================================
__global__ void __launch_bounds__(128) k_fin(
    const float* __restrict__ gamma, const float* __restrict__ beta,
    const float* __restrict__ W2, const float* __restrict__ b2,
    float* __restrict__ out)
{
    __shared__ float4 sW2[64];
    __shared__ float sb2[CH_], ssc[CH_], ssh[CH_];

    int bid = blockIdx.x;
    int tid = threadIdx.x;

    if (bid >= 1600) {
        int base = (bid - 1600)*128 + tid;           // 0..409599
        #pragma unroll
        for (int h = 0; h < 2; h++) {
            int e = base + h*409600;
            int hw4 = e & 1023;
            int bt  = e >> 10;
            int t = bt % FT_;
            int b = bt / FT_;
            const float step = (float)(63.0/399.0);
            float pos = (float)t * step;
            int i0 = (int)pos;
            int i1 = min(i0+1, T_-1);
            float w = pos - (float)i0, w0 = 1.f - w;
            float4 a = ((const float4*)(g_r + (b*T_+i0)*HW_))[hw4];
            float4 c = ((const float4*)(g_r + (b*T_+i1)*HW_))[hw4];
            float4 v = make_float4(a.x*w0 + c.x*w, a.y*w0 + c.y*w,
                                   a.z*w0 + c.z*w, a.w*w0 + c.w*w);
            ((float4*)(out + OUT_OFF_RESULT))[e] = v;
        }
        return;
    }

    if (tid < 64) sW2[tid] = ((const float4*)W2)[tid];
    if (tid < CH_) {
        int o = tid;
        sb2[o] = b2[o];
        float mean = g_ss[o]    * (1.f/(float)CNT_);
        float var  = g_ss[o+16] * (1.f/(float)CNT_) - mean*mean;
        float sc = gamma[o] * rsqrtf(var + 1e-5f);
        ssc[o] = sc;
        ssh[o] = beta[o] - mean*sc;
    }
    __syncthreads();

    int b = (bid >= 800) ? 1 : 0;
    int slab = bid - b*800;                // 0..799
    int l0 = slab * 256;
    int t = l0 >> 9;
    int n0 = l0 & (N_-1);
    const float step = (float)(63.0/399.0);
    float pos = (float)t * step;
    int i0 = (int)pos;
    int i1 = min(i0+1, T_-1);
    float w = pos - (float)i0, w0 = 1.f - w;

    const float4* gf4 = (const float4*)g_f;
    float hr[2][CH_];
    #pragma unroll
    for (int j = 0; j < 2; j++) {
        int bn = b*N_ + n0 + tid + j*128;
        #pragma unroll
        for (int q = 0; q < 4; q++) {
            float4 av = gf4[(size_t)(i0*4+q)*BN_ + bn];
            float4 cv = gf4[(size_t)(i1*4+q)*BN_ + bn];
            hr[j][q*4+0] = fmaxf(ssc[q*4+0]*(av.x*w0 + cv.x*w) + ssh[q*4+0], 0.f);
            hr[j][q*4+1] = fmaxf(ssc[q*4+1]*(av.y*w0 + cv.y*w) + ssh[q*4+1], 0.f);
            hr[j][q*4+2] = fmaxf(ssc[q*4+2]*(av.z*w0 + cv.z*w) + ssh[q*4+2], 0.f);
            hr[j][q*4+3] = fmaxf(ssc[q*4+3]*(av.w*w0 + cv.w*w) + ssh[q*4+3], 0.f);
        }
    }

    float* outp = out + (size_t)b*CH_*L_ + (size_t)t*N_ + n0 + tid;
    #pragma unroll
    for (int o2 = 0; o2 < CH_; o2++) {
        float4 wa = sW2[o2*4+0], wb = sW2[o2*4+1], wc = sW2[o2*4+2], wd = sW2[o2*4+3];
        float bb = sb2[o2];
        #pragma unroll
        for (int j = 0; j < 2; j++) {
            float acc = bb;
            acc += wa.x*hr[j][0];  acc += wa.y*hr[j][1];
            acc += wa.z*hr[j][2];  acc += wa.w*hr[j][3];
            acc += wb.x*hr[j][4];  acc += wb.y*hr[j][5];
            acc += wb.z*hr[j][6];  acc += wb.w*hr[j][7];
            acc += wc.x*hr[j][8];  acc += wc.y*hr[j][9];
            acc += wc.z*hr[j][10]; acc += wc.w*hr[j][11];
            acc += wd.x*hr[j][12]; acc += wd.y*hr[j][13];
            acc += wd.z*hr[j][14]; acc += wd.w*hr[j][15];
            outp[(size_t)o2*L_ + j*128] = acc;
        }
    }
}

extern "C" void kernel_launch(void* const* d_in, const int* in_sizes, int n_in,
                              void* d_out, int out_size) {
    const float* x     = (const float*)d_in[0];
    const int*   coord = (const int*)  d_in[1];
    const float* Wf    = (const float*)d_in[2];
    const float* bf    = (const float*)d_in[3];
    const float* Wr    = (const float*)d_in[4];
    const float* br    = (const float*)d_in[5];
    const float* W1    = (const float*)d_in[6];
    const float* b1    = (const float*)d_in[7];
    const float* gamma = (const float*)d_in[8];
    const float* beta  = (const float*)d_in[9];
    const float* W2    = (const float*)d_in[10];
    const float* b2    = (const float*)d_in[11];
    float* out = (float*)d_out;

    k_prep <<<1,    128>>>(coord, W1, Wf, b1, bf);
    k_main <<<1536, 128>>>(x, Wr, br);
    k_stats<<<1024, 128>>>();
    k_fin  <<<4800, 128>>>(gamma, beta, W2, b2, out);
}